// round 7
// baseline (speedup 1.0000x reference)
#include <cuda_runtime.h>
#include <cuda_bf16.h>
#include <cstdint>

#define BATCH 8
#define NPTS  4096
#define DDIM  512
#define NT    32          // 4096 / 128 tiles per dim
#define PAIRS 528         // NT*(NT+1)/2
#define BK    128         // s8 k-elements per chunk (128B rows)
#define NCHUNK 4          // DDIM/BK
#define STAGE_BYTES 32768 // A 16KB + B 16KB (s8, 128 rows x 128B)
#define NSTAGE 3
#define SMEM_DYN (NSTAGE * STAGE_BYTES)   // 96 KB

// Scratch: s8 quantized x (per-row scale), per-point sq, 1/(1-sq), dequant f
__device__ int8_t g_xq[(size_t)BATCH * NPTS * DDIM];
__device__ float g_sq[BATCH * NPTS];
__device__ float g_inv[BATCH * NPTS];
__device__ float g_f[BATCH * NPTS];

// ---------------------------------------------------------------- prep ----
__global__ void prep_kernel(const float* __restrict__ emb) {
    int row = blockIdx.x;               // b*NPTS + n
    int tid = threadIdx.x;              // 128 threads
    float4 v = ((const float4*)(emb + (size_t)row * DDIM))[tid];

    float s = fmaf(v.x, v.x, fmaf(v.y, v.y, fmaf(v.z, v.z, v.w * v.w)));
    float m = fmaxf(fmaxf(fabsf(v.x), fabsf(v.y)), fmaxf(fabsf(v.z), fabsf(v.w)));
    __shared__ float red[4], redm[4];
#pragma unroll
    for (int o = 16; o > 0; o >>= 1) {
        s += __shfl_down_sync(0xffffffffu, s, o);
        m = fmaxf(m, __shfl_down_sync(0xffffffffu, m, o));
    }
    if ((tid & 31) == 0) { red[tid >> 5] = s; redm[tid >> 5] = m; }
    __syncthreads();
    float tot = red[0] + red[1] + red[2] + red[3];
    float mx  = fmaxf(fmaxf(redm[0], redm[1]), fmaxf(redm[2], redm[3]));

    if (sqrtf(tot) >= 1.f) {            // __proj (faithful; won't trigger here)
        float invn = rsqrtf(tot);
        v.x = v.x * invn - 1e-5f; v.y = v.y * invn - 1e-5f;
        v.z = v.z * invn - 1e-5f; v.w = v.w * invn - 1e-5f;
        float s2 = fmaf(v.x, v.x, fmaf(v.y, v.y, fmaf(v.z, v.z, v.w * v.w)));
        float m2 = fmaxf(fmaxf(fabsf(v.x), fabsf(v.y)), fmaxf(fabsf(v.z), fabsf(v.w)));
#pragma unroll
        for (int o = 16; o > 0; o >>= 1) {
            s2 += __shfl_down_sync(0xffffffffu, s2, o);
            m2 = fmaxf(m2, __shfl_down_sync(0xffffffffu, m2, o));
        }
        __syncthreads();
        if ((tid & 31) == 0) { red[tid >> 5] = s2; redm[tid >> 5] = m2; }
        __syncthreads();
        tot = red[0] + red[1] + red[2] + red[3];
        mx  = fmaxf(fmaxf(redm[0], redm[1]), fmaxf(redm[2], redm[3]));
    }

    float qs = (mx > 0.f) ? 127.f / mx : 0.f;
    int q0 = __float2int_rn(v.x * qs);
    int q1 = __float2int_rn(v.y * qs);
    int q2 = __float2int_rn(v.z * qs);
    int q3 = __float2int_rn(v.w * qs);
    q0 = max(-127, min(127, q0)); q1 = max(-127, min(127, q1));
    q2 = max(-127, min(127, q2)); q3 = max(-127, min(127, q3));
    uint32_t pk = (uint32_t)(q0 & 0xff) | ((uint32_t)(q1 & 0xff) << 8) |
                  ((uint32_t)(q2 & 0xff) << 16) | ((uint32_t)(q3 & 0xff) << 24);
    ((uint32_t*)(g_xq + (size_t)row * DDIM))[tid] = pk;
    if (tid == 0) {
        g_sq[row]  = tot;
        g_inv[row] = 1.f / (1.f - tot);
        g_f[row]   = mx * (1.f / 127.f);
    }
}

// ------------------------------------------------------------- helpers ----
__device__ __forceinline__ void cp_async16(uint32_t dst, const void* src) {
    asm volatile("cp.async.cg.shared.global [%0], [%1], 16;\n" :: "r"(dst), "l"(src));
}
__device__ __forceinline__ void cp_commit() {
    asm volatile("cp.async.commit_group;\n" ::);
}
template <int N>
__device__ __forceinline__ void cp_wait() {
    asm volatile("cp.async.wait_group %0;\n" :: "n"(N));
}
__device__ __forceinline__ void ldsm_x4(uint32_t& r0, uint32_t& r1,
                                        uint32_t& r2, uint32_t& r3, uint32_t a) {
    asm volatile("ldmatrix.sync.aligned.m8n8.x4.shared.b16 {%0,%1,%2,%3}, [%4];\n"
                 : "=r"(r0), "=r"(r1), "=r"(r2), "=r"(r3) : "r"(a));
}

__device__ __forceinline__ float hyp_dist(float gv, float sa, float sb,
                                          float ia, float ib, bool diag) {
    float d2 = fmaxf(sa + sb - 2.f * gv, 0.f);
    float dn;
    asm("sqrt.approx.f32 %0, %1;" : "=f"(dn) : "f"(d2));
    float t = 2.f * dn * ia * ib;           // arg = 1 + t
    float w;
    asm("sqrt.approx.f32 %0, %1;" : "=f"(w) : "f"(t * (t + 2.f)));  // sqrt(arg^2-1)
    float arg = 1.f + t + w;
    float lg;
    asm("lg2.approx.f32 %0, %1;" : "=f"(lg) : "f"(arg));
    return (t > 0.f && !diag) ? lg * 0.69314718055994531f : 0.f;
}

// ---------------------------------------------------------------- gemm ----
__global__ void __launch_bounds__(256, 2)
gram_dist_kernel(float* __restrict__ out) {
    extern __shared__ __align__(1024) char smem_raw[];
    __shared__ float s_sqi[128], s_invi[128], s_fi[128];
    __shared__ float s_sqj[128], s_invj[128], s_fj[128];

    const int b  = blockIdx.y;
    const int bN = b * NPTS;

    // pair index -> (ti, tj), ti <= tj
    int p = blockIdx.x, ti = 0;
    while (p >= NT - ti) { p -= NT - ti; ++ti; }
    const int tj = ti + p;
    const bool diagT = (ti == tj);

    const int tid  = threadIdx.x;
    const int warp = tid >> 5;
    const int lane = tid & 31;
    const int g  = lane >> 2;           // 0..7
    const int t2 = (lane & 3) * 2;      // 0,2,4,6
    const int wm = warp & 1;            // 2 m-blocks of 64
    const int wn = warp >> 1;           // 4 n-blocks of 32

    const uint32_t sbase0 = (uint32_t)__cvta_generic_to_shared(smem_raw);
    float* stageT = (float*)smem_raw;   // epilogue reuse

    // per-row/col epilogue params
    if (tid < 128) {
        s_sqi[tid]  = g_sq[bN + ti * 128 + tid];
        s_invi[tid] = g_inv[bN + ti * 128 + tid];
        s_fi[tid]   = g_f[bN + ti * 128 + tid];
    } else {
        int u = tid - 128;
        s_sqj[u]  = g_sq[bN + tj * 128 + u];
        s_invj[u] = g_inv[bN + tj * 128 + u];
        s_fj[u]   = g_f[bN + tj * 128 + u];
    }

    // --- stage loader: 2048 16B chunks (A 1024, B 1024), 8 per thread ---
    // Row = 128 s8 = 128B = 8 chunks. XOR swizzle: chunk c ^= row&7.
    const size_t rowA_g = (size_t)(bN + ti * 128) * DDIM;
    const size_t rowB_g = (size_t)(bN + tj * 128) * DDIM;
    auto load_stage = [&](int s, int k0) {
        uint32_t sb = sbase0 + (uint32_t)s * STAGE_BYTES;
#pragma unroll
        for (int i = 0; i < 8; ++i) {
            int chunk = i * 256 + tid;
            int tile  = chunk >> 10;       // 0 = A, 1 = B
            int cid   = chunk & 1023;
            int row   = cid >> 3;
            int c     = cid & 7;
            const int8_t* src =
                g_xq + (tile ? rowB_g : rowA_g) + (size_t)row * DDIM + k0 + c * 16;
            uint32_t dst = sb + (uint32_t)(tile * 16384 + row * 128 + ((c ^ (row & 7)) << 4));
            cp_async16(dst, src);
        }
    };

    // per-thread ldmatrix geometry (b16 view of s8 rows; same as bf16 code)
    const int swz = lane & 7;
    const int dcA = lane >> 4;                              // 0/1 (16B half)
    const int dcB = (lane >> 3) & 1;                        // 0/1
    uint32_t aByte[4], bByte[2];
#pragma unroll
    for (int mt = 0; mt < 4; ++mt)
        aByte[mt] = (uint32_t)((wm * 64 + mt * 16 + (lane & 15)) * 128);
#pragma unroll
    for (int pp = 0; pp < 2; ++pp)
        bByte[pp] = (uint32_t)(16384 + (wn * 32 + pp * 16 + (lane & 7) + ((lane >> 4) << 3)) * 128);

    int acc[4][4][4];
#pragma unroll
    for (int a = 0; a < 4; ++a)
#pragma unroll
        for (int c = 0; c < 4; ++c)
#pragma unroll
            for (int r = 0; r < 4; ++r) acc[a][c][r] = 0;

    load_stage(0, 0);  cp_commit();
    load_stage(1, BK); cp_commit();

    for (int kb = 0; kb < NCHUNK; ++kb) {
        if (kb < NCHUNK - 1) cp_wait<1>(); else cp_wait<0>();
        __syncthreads();
        if (kb + 2 < NCHUNK) { load_stage((kb + 2) % NSTAGE, (kb + 2) * BK); cp_commit(); }

        uint32_t sb = sbase0 + (uint32_t)(kb % NSTAGE) * STAGE_BYTES;
#pragma unroll
        for (int ks = 0; ks < 4; ++ks) {            // 4 k32-steps per 128B row
            const int c0 = ks * 2;
            const uint32_t cA = (uint32_t)(((c0 | dcA) ^ swz) << 4);
            const uint32_t cB = (uint32_t)(((c0 | dcB) ^ swz) << 4);
            uint32_t afr[4][4], bfr[4][2];
#pragma unroll
            for (int mt = 0; mt < 4; ++mt)
                ldsm_x4(afr[mt][0], afr[mt][1], afr[mt][2], afr[mt][3],
                        sb + aByte[mt] + cA);
#pragma unroll
            for (int pp = 0; pp < 2; ++pp)
                ldsm_x4(bfr[2 * pp][0], bfr[2 * pp][1], bfr[2 * pp + 1][0], bfr[2 * pp + 1][1],
                        sb + bByte[pp] + cB);
#pragma unroll
            for (int mt = 0; mt < 4; ++mt)
#pragma unroll
                for (int nt = 0; nt < 4; ++nt) {
                    asm volatile(
                        "mma.sync.aligned.m16n8k32.row.col.s32.s8.s8.s32 "
                        "{%0,%1,%2,%3}, {%4,%5,%6,%7}, {%8,%9}, {%0,%1,%2,%3};\n"
                        : "+r"(acc[mt][nt][0]), "+r"(acc[mt][nt][1]),
                          "+r"(acc[mt][nt][2]), "+r"(acc[mt][nt][3])
                        : "r"(afr[mt][0]), "r"(afr[mt][1]),
                          "r"(afr[mt][2]), "r"(afr[mt][3]),
                          "r"(bfr[nt][0]), "r"(bfr[nt][1]));
                }
        }
    }

    // ---------------- epilogue 1: dequant + distances + direct stores ------
    float* outB = out + (size_t)b * NPTS * NPTS;
    const uint32_t gi0 = (uint32_t)(ti * 128);
    const uint32_t gj0 = (uint32_t)(tj * 128);

#pragma unroll
    for (int mt = 0; mt < 4; ++mt) {
        const int rl = wm * 64 + mt * 16 + g;
#pragma unroll
        for (int nt = 0; nt < 4; ++nt) {
            const int cl = wn * 32 + nt * 8 + t2;
            const float sb0 = s_sqj[cl],     ib0 = s_invj[cl],     fj0 = s_fj[cl];
            const float sb1 = s_sqj[cl + 1], ib1 = s_invj[cl + 1], fj1 = s_fj[cl + 1];
#pragma unroll
            for (int h = 0; h < 2; ++h) {
                const int rr = rl + h * 8;
                const float sa = s_sqi[rr], ia = s_invi[rr], fi = s_fi[rr];
                const bool dg = diagT && (rr == cl);
                float g0 = __int2float_rn(acc[mt][nt][h * 2 + 0]) * (fi * fj0);
                float g1 = __int2float_rn(acc[mt][nt][h * 2 + 1]) * (fi * fj1);
                float v0 = hyp_dist(g0, sa, sb0, ia, ib0, dg);
                float v1 = hyp_dist(g1, sa, sb1, ia, ib1, diagT && (rr == cl + 1));
                acc[mt][nt][h * 2 + 0] = __float_as_int(v0);
                acc[mt][nt][h * 2 + 1] = __float_as_int(v1);
                float2 pk; pk.x = v0; pk.y = v1;
                *(float2*)(outB + ((gi0 + rr) * (uint32_t)NPTS + gj0 + cl)) = pk;
            }
        }
    }

    // ---------------- epilogue 2: mirror via smem staging ------------------
    __syncthreads();                    // gemm smem reads fully done
    for (int jc = 0; jc < 4; ++jc) {    // 4 groups of 32 cols
        if (!diagT && wn == jc) {
#pragma unroll
            for (int mt = 0; mt < 4; ++mt) {
#pragma unroll
                for (int nt = 0; nt < 4; ++nt) {
                    int c = nt * 8 + t2;
                    float* tp = stageT + c * 132;
#pragma unroll
                    for (int h = 0; h < 2; ++h) {
                        int r = wm * 64 + mt * 16 + g + h * 8;
                        tp[r]       = __int_as_float(acc[mt][nt][h * 2 + 0]);
                        tp[132 + r] = __int_as_float(acc[mt][nt][h * 2 + 1]);
                    }
                }
            }
        }
        __syncthreads();
        if (!diagT) {
            // 32 rows x 128 floats = 1024 float4, 256 threads x 4
#pragma unroll
            for (int it = 0; it < 4; ++it) {
                int idx = it * 256 + tid;
                int row = idx >> 5;          // 0..31
                int q   = idx & 31;
                float4 v = *(const float4*)&stageT[row * 132 + q * 4];
                uint32_t gj = gj0 + (uint32_t)(jc * 32 + row);
                *(float4*)(outB + (gj * (uint32_t)NPTS + gi0 + (uint32_t)(q * 4))) = v;
            }
        }
        __syncthreads();
    }
}

// -------------------------------------------------------------- launch ----
extern "C" void kernel_launch(void* const* d_in, const int* in_sizes, int n_in,
                              void* d_out, int out_size) {
    const float* emb = (const float*)d_in[0];
    float* out = (float*)d_out;

    prep_kernel<<<BATCH * NPTS, 128>>>(emb);

    cudaFuncSetAttribute(gram_dist_kernel,
                         cudaFuncAttributeMaxDynamicSharedMemorySize, SMEM_DYN);
    dim3 grid(PAIRS, BATCH);
    gram_dist_kernel<<<grid, 256, SMEM_DYN>>>(out);
}

// round 8
// speedup vs baseline: 1.6887x; 1.6887x over previous
#include <cuda_runtime.h>
#include <cuda_bf16.h>
#include <cstdint>

#define BATCH 8
#define NPTS  4096
#define DDIM  512
#define NT    32          // 4096 / 128 tiles per dim
#define PAIRS 528         // NT*(NT+1)/2
#define BK    64
#define NCHUNK 8          // DDIM/BK
#define STAGE_BYTES 32768 // A 16KB + B 16KB (bf16, 128 rows x 64 cols)
#define NSTAGE 3
#define SMEM_DYN (NSTAGE * STAGE_BYTES)   // 96 KB -> 2 CTA/SM

__device__ __nv_bfloat16 g_xb[(size_t)BATCH * NPTS * DDIM];
__device__ float g_sq[BATCH * NPTS];
__device__ float g_inv[BATCH * NPTS];

// ---------------------------------------------------------------- prep ----
__global__ void prep_kernel(const float* __restrict__ emb) {
    int row = blockIdx.x;               // b*NPTS + n
    int tid = threadIdx.x;              // 128 threads
    float4 v = ((const float4*)(emb + (size_t)row * DDIM))[tid];

    float s = fmaf(v.x, v.x, fmaf(v.y, v.y, fmaf(v.z, v.z, v.w * v.w)));
    __shared__ float red[4];
#pragma unroll
    for (int o = 16; o > 0; o >>= 1) s += __shfl_down_sync(0xffffffffu, s, o);
    if ((tid & 31) == 0) red[tid >> 5] = s;
    __syncthreads();
    float tot = red[0] + red[1] + red[2] + red[3];

    if (sqrtf(tot) >= 1.f) {            // __proj (faithful; won't trigger here)
        float invn = rsqrtf(tot);
        v.x = v.x * invn - 1e-5f; v.y = v.y * invn - 1e-5f;
        v.z = v.z * invn - 1e-5f; v.w = v.w * invn - 1e-5f;
        float s2 = fmaf(v.x, v.x, fmaf(v.y, v.y, fmaf(v.z, v.z, v.w * v.w)));
#pragma unroll
        for (int o = 16; o > 0; o >>= 1) s2 += __shfl_down_sync(0xffffffffu, s2, o);
        __syncthreads();
        if ((tid & 31) == 0) red[tid >> 5] = s2;
        __syncthreads();
        tot = red[0] + red[1] + red[2] + red[3];
    }

    __nv_bfloat162 p0 = __floats2bfloat162_rn(v.x, v.y);
    __nv_bfloat162 p1 = __floats2bfloat162_rn(v.z, v.w);
    uint2 u;
    u.x = *(uint32_t*)&p0;
    u.y = *(uint32_t*)&p1;
    ((uint2*)(g_xb + (size_t)row * DDIM))[tid] = u;
    if (tid == 0) {
        g_sq[row]  = tot;
        g_inv[row] = 1.f / (1.f - tot);
    }
}

// ------------------------------------------------------------- helpers ----
__device__ __forceinline__ void cp_async16(uint32_t dst, const void* src) {
    asm volatile("cp.async.cg.shared.global [%0], [%1], 16;\n" :: "r"(dst), "l"(src));
}
__device__ __forceinline__ void cp_commit() {
    asm volatile("cp.async.commit_group;\n" ::);
}
template <int N>
__device__ __forceinline__ void cp_wait() {
    asm volatile("cp.async.wait_group %0;\n" :: "n"(N));
}
__device__ __forceinline__ void ldsm_x4(uint32_t& r0, uint32_t& r1,
                                        uint32_t& r2, uint32_t& r3, uint32_t a) {
    asm volatile("ldmatrix.sync.aligned.m8n8.x4.shared.b16 {%0,%1,%2,%3}, [%4];\n"
                 : "=r"(r0), "=r"(r1), "=r"(r2), "=r"(r3) : "r"(a));
}

__device__ __forceinline__ float hyp_dist(float gv, float sa, float sb,
                                          float ia, float ib, bool diag) {
    float d2 = fmaxf(sa + sb - 2.f * gv, 0.f);
    float dn;
    asm("sqrt.approx.f32 %0, %1;" : "=f"(dn) : "f"(d2));
    float t = 2.f * dn * ia * ib;           // arg = 1 + t
    float w;
    asm("sqrt.approx.f32 %0, %1;" : "=f"(w) : "f"(t * (t + 2.f)));  // sqrt(arg^2-1)
    float arg = 1.f + t + w;
    float lg;
    asm("lg2.approx.f32 %0, %1;" : "=f"(lg) : "f"(arg));
    return (t > 0.f && !diag) ? lg * 0.69314718055994531f : 0.f;
}

// ---------------------------------------------------------------- gemm ----
__global__ void __launch_bounds__(512, 2)
gram_dist_kernel(float* __restrict__ out) {
    extern __shared__ __align__(1024) char smem_raw[];
    __shared__ float s_sqi[128], s_invi[128], s_sqj[128], s_invj[128];

    const int b  = blockIdx.y;
    const int bN = b * NPTS;

    // pair index -> (ti, tj), ti <= tj
    int p = blockIdx.x, ti = 0;
    while (p >= NT - ti) { p -= NT - ti; ++ti; }
    const int tj = ti + p;
    const bool diagT = (ti == tj);

    const int tid  = threadIdx.x;
    const int warp = tid >> 5;
    const int lane = tid & 31;
    const int g  = lane >> 2;           // 0..7
    const int t2 = (lane & 3) * 2;      // 0,2,4,6
    const int wm = warp & 3;            // 4 m-quarters of 32 rows
    const int wn = warp >> 2;           // 4 n-quarters of 32 cols

    const uint32_t sbase0 = (uint32_t)__cvta_generic_to_shared(smem_raw);
    float* stageT = (float*)smem_raw;   // epilogue reuse

    // per-row/col epilogue params
    if (tid < 128) {
        s_sqi[tid]  = g_sq[bN + ti * 128 + tid];
        s_invi[tid] = g_inv[bN + ti * 128 + tid];
    } else if (tid < 256) {
        int u = tid - 128;
        s_sqj[u]  = g_sq[bN + tj * 128 + u];
        s_invj[u] = g_inv[bN + tj * 128 + u];
    }

    // --- stage loader: 2048 16B chunks (A 1024, B 1024), 4 per thread ---
    // Row layout: 128 rows x 64 bf16 (128B = 8 chunks). XOR swizzle c ^= row&7.
    const size_t rowA_g = (size_t)(bN + ti * 128) * DDIM;
    const size_t rowB_g = (size_t)(bN + tj * 128) * DDIM;
    auto load_stage = [&](int s, int k0) {
        uint32_t sb = sbase0 + (uint32_t)s * STAGE_BYTES;
#pragma unroll
        for (int i = 0; i < 4; ++i) {
            int chunk = i * 512 + tid;
            int tile  = chunk >> 10;       // 0 = A, 1 = B
            int cid   = chunk & 1023;
            int row   = cid >> 3;
            int c     = cid & 7;
            const __nv_bfloat16* src =
                g_xb + (tile ? rowB_g : rowA_g) + (size_t)row * DDIM + k0 + c * 8;
            uint32_t dst = sb + (uint32_t)(tile * 16384 + row * 128 + ((c ^ (row & 7)) << 4));
            cp_async16(dst, src);
        }
    };

    // per-thread ldmatrix geometry
    const int swz = lane & 7;
    const int dcA = lane >> 4;                              // 0/1 (16B half)
    const int dcB = (lane >> 3) & 1;                        // 0/1
    uint32_t aByte[2], bByte[2];
#pragma unroll
    for (int mt = 0; mt < 2; ++mt)
        aByte[mt] = (uint32_t)((wm * 32 + mt * 16 + (lane & 15)) * 128);
#pragma unroll
    for (int pp = 0; pp < 2; ++pp)
        bByte[pp] = (uint32_t)(16384 + (wn * 32 + pp * 16 + (lane & 7) + ((lane >> 4) << 3)) * 128);

    float acc[2][4][4];
#pragma unroll
    for (int a = 0; a < 2; ++a)
#pragma unroll
        for (int c = 0; c < 4; ++c)
#pragma unroll
            for (int r = 0; r < 4; ++r) acc[a][c][r] = 0.f;

    load_stage(0, 0);  cp_commit();
    load_stage(1, BK); cp_commit();

    for (int kb = 0; kb < NCHUNK; ++kb) {
        if (kb < NCHUNK - 1) cp_wait<1>(); else cp_wait<0>();
        __syncthreads();
        if (kb + 2 < NCHUNK) { load_stage((kb + 2) % NSTAGE, (kb + 2) * BK); cp_commit(); }

        uint32_t sb = sbase0 + (uint32_t)(kb % NSTAGE) * STAGE_BYTES;
#pragma unroll
        for (int kk = 0; kk < BK; kk += 16) {
            const int c0 = kk >> 3;                          // 0,2,4,6
            const uint32_t cA = (uint32_t)(((c0 | dcA) ^ swz) << 4);
            const uint32_t cB = (uint32_t)(((c0 | dcB) ^ swz) << 4);
            uint32_t afr[2][4], bfr[4][2];
#pragma unroll
            for (int mt = 0; mt < 2; ++mt)
                ldsm_x4(afr[mt][0], afr[mt][1], afr[mt][2], afr[mt][3],
                        sb + aByte[mt] + cA);
#pragma unroll
            for (int pp = 0; pp < 2; ++pp)
                ldsm_x4(bfr[2 * pp][0], bfr[2 * pp][1], bfr[2 * pp + 1][0], bfr[2 * pp + 1][1],
                        sb + bByte[pp] + cB);
#pragma unroll
            for (int mt = 0; mt < 2; ++mt)
#pragma unroll
                for (int nt = 0; nt < 4; ++nt) {
                    asm volatile(
                        "mma.sync.aligned.m16n8k16.row.col.f32.bf16.bf16.f32 "
                        "{%0,%1,%2,%3}, {%4,%5,%6,%7}, {%8,%9}, {%0,%1,%2,%3};\n"
                        : "+f"(acc[mt][nt][0]), "+f"(acc[mt][nt][1]),
                          "+f"(acc[mt][nt][2]), "+f"(acc[mt][nt][3])
                        : "r"(afr[mt][0]), "r"(afr[mt][1]),
                          "r"(afr[mt][2]), "r"(afr[mt][3]),
                          "r"(bfr[nt][0]), "r"(bfr[nt][1]));
                }
        }
    }

    // ---------------- epilogue 1: distances + direct stores ----------------
    float* outB = out + (size_t)b * NPTS * NPTS;
    const uint32_t gi0 = (uint32_t)(ti * 128);
    const uint32_t gj0 = (uint32_t)(tj * 128);

#pragma unroll
    for (int mt = 0; mt < 2; ++mt) {
        const int rl = wm * 32 + mt * 16 + g;
#pragma unroll
        for (int nt = 0; nt < 4; ++nt) {
            const int cl = wn * 32 + nt * 8 + t2;
            const float sb0 = s_sqj[cl],     ib0 = s_invj[cl];
            const float sb1 = s_sqj[cl + 1], ib1 = s_invj[cl + 1];
#pragma unroll
            for (int h = 0; h < 2; ++h) {
                const int rr = rl + h * 8;
                const float sa = s_sqi[rr], ia = s_invi[rr];
                float v0 = hyp_dist(acc[mt][nt][h * 2 + 0], sa, sb0, ia, ib0,
                                    diagT && (rr == cl));
                float v1 = hyp_dist(acc[mt][nt][h * 2 + 1], sa, sb1, ia, ib1,
                                    diagT && (rr == cl + 1));
                acc[mt][nt][h * 2 + 0] = v0;
                acc[mt][nt][h * 2 + 1] = v1;
                float2 pk; pk.x = v0; pk.y = v1;
                *(float2*)(outB + ((gi0 + rr) * (uint32_t)NPTS + gj0 + cl)) = pk;
            }
        }
    }

    // ---------------- epilogue 2: mirror via smem staging ------------------
    __syncthreads();                    // gemm smem reads fully done
    for (int jc = 0; jc < 4; ++jc) {    // 4 groups of 32 cols
        if (!diagT && wn == jc) {
#pragma unroll
            for (int mt = 0; mt < 2; ++mt) {
#pragma unroll
                for (int nt = 0; nt < 4; ++nt) {
                    int c = nt * 8 + t2;
                    float* tp = stageT + c * 132;
#pragma unroll
                    for (int h = 0; h < 2; ++h) {
                        int r = wm * 32 + mt * 16 + g + h * 8;
                        tp[r]       = acc[mt][nt][h * 2 + 0];
                        tp[132 + r] = acc[mt][nt][h * 2 + 1];
                    }
                }
            }
        }
        __syncthreads();
        if (!diagT) {
            // 32 rows x 128 floats = 1024 float4, 512 threads x 2
#pragma unroll
            for (int it = 0; it < 2; ++it) {
                int idx = it * 512 + tid;
                int row = idx >> 5;          // 0..31
                int q   = idx & 31;
                float4 v = *(const float4*)&stageT[row * 132 + q * 4];
                uint32_t gj = gj0 + (uint32_t)(jc * 32 + row);
                *(float4*)(outB + (gj * (uint32_t)NPTS + gi0 + (uint32_t)(q * 4))) = v;
            }
        }
        __syncthreads();
    }
}

// -------------------------------------------------------------- launch ----
extern "C" void kernel_launch(void* const* d_in, const int* in_sizes, int n_in,
                              void* d_out, int out_size) {
    const float* emb = (const float*)d_in[0];
    float* out = (float*)d_out;

    prep_kernel<<<BATCH * NPTS, 128>>>(emb);

    cudaFuncSetAttribute(gram_dist_kernel,
                         cudaFuncAttributeMaxDynamicSharedMemorySize, SMEM_DYN);
    dim3 grid(PAIRS, BATCH);
    gram_dist_kernel<<<grid, 512, SMEM_DYN>>>(out);
}

// round 9
// speedup vs baseline: 1.8397x; 1.0894x over previous
#include <cuda_runtime.h>
#include <cuda_fp16.h>
#include <cstdint>

#define BATCH 8
#define NPTS  4096
#define DDIM  512
#define NT    32          // 4096 / 128 tiles per dim
#define PAIRS 528         // NT*(NT+1)/2
#define BK    64
#define NCHUNK 8          // DDIM/BK
#define STAGE_BYTES 32768 // A 16KB + B 16KB (f16, 128 rows x 64 cols)
#define NSTAGE 3
#define SMEM_DYN (NSTAGE * STAGE_BYTES)   // 96 KB -> 2 CTA/SM

__device__ __half g_xh[(size_t)BATCH * NPTS * DDIM];
__device__ float g_sq[BATCH * NPTS];
__device__ float g_inv[BATCH * NPTS];

// ---------------------------------------------------------------- prep ----
__global__ void prep_kernel(const float* __restrict__ emb) {
    int row = blockIdx.x;               // b*NPTS + n
    int tid = threadIdx.x;              // 128 threads
    float4 v = ((const float4*)(emb + (size_t)row * DDIM))[tid];

    float s = fmaf(v.x, v.x, fmaf(v.y, v.y, fmaf(v.z, v.z, v.w * v.w)));
    __shared__ float red[4];
#pragma unroll
    for (int o = 16; o > 0; o >>= 1) s += __shfl_down_sync(0xffffffffu, s, o);
    if ((tid & 31) == 0) red[tid >> 5] = s;
    __syncthreads();
    float tot = red[0] + red[1] + red[2] + red[3];

    if (sqrtf(tot) >= 1.f) {            // __proj (faithful; won't trigger here)
        float invn = rsqrtf(tot);
        v.x = v.x * invn - 1e-5f; v.y = v.y * invn - 1e-5f;
        v.z = v.z * invn - 1e-5f; v.w = v.w * invn - 1e-5f;
        float s2 = fmaf(v.x, v.x, fmaf(v.y, v.y, fmaf(v.z, v.z, v.w * v.w)));
#pragma unroll
        for (int o = 16; o > 0; o >>= 1) s2 += __shfl_down_sync(0xffffffffu, s2, o);
        __syncthreads();
        if ((tid & 31) == 0) red[tid >> 5] = s2;
        __syncthreads();
        tot = red[0] + red[1] + red[2] + red[3];
    }

    __half2 p0 = __floats2half2_rn(v.x, v.y);
    __half2 p1 = __floats2half2_rn(v.z, v.w);
    uint2 u;
    u.x = *(uint32_t*)&p0;
    u.y = *(uint32_t*)&p1;
    ((uint2*)(g_xh + (size_t)row * DDIM))[tid] = u;
    if (tid == 0) {
        g_sq[row]  = tot;
        g_inv[row] = 1.f / (1.f - tot);
    }
}

// ------------------------------------------------------------- helpers ----
__device__ __forceinline__ void cp_async16(uint32_t dst, const void* src) {
    asm volatile("cp.async.cg.shared.global [%0], [%1], 16;\n" :: "r"(dst), "l"(src));
}
__device__ __forceinline__ void cp_commit() {
    asm volatile("cp.async.commit_group;\n" ::);
}
template <int N>
__device__ __forceinline__ void cp_wait() {
    asm volatile("cp.async.wait_group %0;\n" :: "n"(N));
}
__device__ __forceinline__ void ldsm_x4(uint32_t& r0, uint32_t& r1,
                                        uint32_t& r2, uint32_t& r3, uint32_t a) {
    asm volatile("ldmatrix.sync.aligned.m8n8.x4.shared.b16 {%0,%1,%2,%3}, [%4];\n"
                 : "=r"(r0), "=r"(r1), "=r"(r2), "=r"(r3) : "r"(a));
}

__device__ __forceinline__ float hyp_dist(float gv, float sa, float sb,
                                          float ia, float ib, bool diag) {
    float d2 = fmaxf(sa + sb - 2.f * gv, 0.f);
    float dn;
    asm("sqrt.approx.f32 %0, %1;" : "=f"(dn) : "f"(d2));
    float t = 2.f * dn * ia * ib;           // arg = 1 + t
    float w;
    asm("sqrt.approx.f32 %0, %1;" : "=f"(w) : "f"(t * (t + 2.f)));  // sqrt(arg^2-1)
    float arg = 1.f + t + w;
    float lg;
    asm("lg2.approx.f32 %0, %1;" : "=f"(lg) : "f"(arg));
    return (t > 0.f && !diag) ? lg * 0.69314718055994531f : 0.f;
}

// ---------------------------------------------------------------- gemm ----
__global__ void __launch_bounds__(256, 2)
gram_dist_kernel(float* __restrict__ out) {
    extern __shared__ __align__(1024) char smem_raw[];
    __shared__ float s_sqi[128], s_invi[128], s_sqj[128], s_invj[128];

    const int b  = blockIdx.y;
    const int bN = b * NPTS;

    // pair index -> (ti, tj), ti <= tj
    int p = blockIdx.x, ti = 0;
    while (p >= NT - ti) { p -= NT - ti; ++ti; }
    const int tj = ti + p;
    const bool diagT = (ti == tj);

    const int tid  = threadIdx.x;
    const int warp = tid >> 5;
    const int lane = tid & 31;
    const int g  = lane >> 2;           // 0..7
    const int t2 = (lane & 3) * 2;      // 0,2,4,6
    const int wm = warp & 1;            // 2 m-blocks of 64
    const int wn = warp >> 1;           // 4 n-blocks of 32

    const uint32_t sbase0 = (uint32_t)__cvta_generic_to_shared(smem_raw);
    float* stageT = (float*)smem_raw;   // epilogue reuse

    // per-row/col epilogue params
    if (tid < 128) {
        s_sqi[tid]  = g_sq[bN + ti * 128 + tid];
        s_invi[tid] = g_inv[bN + ti * 128 + tid];
    } else {
        int u = tid - 128;
        s_sqj[u]  = g_sq[bN + tj * 128 + u];
        s_invj[u] = g_inv[bN + tj * 128 + u];
    }

    // --- stage loader: 2048 16B chunks (A 1024, B 1024), 8 per thread ---
    const size_t rowA_g = (size_t)(bN + ti * 128) * DDIM;
    const size_t rowB_g = (size_t)(bN + tj * 128) * DDIM;
    auto load_stage = [&](int s, int k0) {
        uint32_t sb = sbase0 + (uint32_t)s * STAGE_BYTES;
#pragma unroll
        for (int i = 0; i < 8; ++i) {
            int chunk = i * 256 + tid;
            int tile  = chunk >> 10;       // 0 = A, 1 = B
            int cid   = chunk & 1023;
            int row   = cid >> 3;
            int c     = cid & 7;
            const __half* src =
                g_xh + (tile ? rowB_g : rowA_g) + (size_t)row * DDIM + k0 + c * 8;
            uint32_t dst = sb + (uint32_t)(tile * 16384 + row * 128 + ((c ^ (row & 7)) << 4));
            cp_async16(dst, src);
        }
    };

    // per-thread ldmatrix geometry (chunk-invariant; hoisted)
    const int swz = lane & 7;
    const int dcA = lane >> 4;
    const int dcB = (lane >> 3) & 1;
    uint32_t aByte[4], bByte[2], cAo[4], cBo[4];
#pragma unroll
    for (int mt = 0; mt < 4; ++mt)
        aByte[mt] = (uint32_t)((wm * 64 + mt * 16 + (lane & 15)) * 128);
#pragma unroll
    for (int pp = 0; pp < 2; ++pp)
        bByte[pp] = (uint32_t)(16384 + (wn * 32 + pp * 16 + (lane & 7) + ((lane >> 4) << 3)) * 128);
#pragma unroll
    for (int ks = 0; ks < 4; ++ks) {
        cAo[ks] = (uint32_t)((((ks * 2) | dcA) ^ swz) << 4);
        cBo[ks] = (uint32_t)((((ks * 2) | dcB) ^ swz) << 4);
    }

    uint32_t acc[4][4][2];              // f16x2 accumulators
#pragma unroll
    for (int a = 0; a < 4; ++a)
#pragma unroll
        for (int c = 0; c < 4; ++c) { acc[a][c][0] = 0u; acc[a][c][1] = 0u; }

    load_stage(0, 0);  cp_commit();
    load_stage(1, BK); cp_commit();

    uint32_t afr[2][4][4], bfr[2][4][2];   // double-buffered fragments

    for (int kb = 0; kb < NCHUNK; ++kb) {
        if (kb < NCHUNK - 1) cp_wait<1>(); else cp_wait<0>();
        __syncthreads();
        if (kb + 2 < NCHUNK) { load_stage((kb + 2) % NSTAGE, (kb + 2) * BK); cp_commit(); }

        const uint32_t sb = sbase0 + (uint32_t)(kb % NSTAGE) * STAGE_BYTES;

        // prime fragments for ks = 0
#pragma unroll
        for (int mt = 0; mt < 4; ++mt)
            ldsm_x4(afr[0][mt][0], afr[0][mt][1], afr[0][mt][2], afr[0][mt][3],
                    sb + aByte[mt] + cAo[0]);
#pragma unroll
        for (int pp = 0; pp < 2; ++pp)
            ldsm_x4(bfr[0][2 * pp][0], bfr[0][2 * pp][1],
                    bfr[0][2 * pp + 1][0], bfr[0][2 * pp + 1][1],
                    sb + bByte[pp] + cBo[0]);

#pragma unroll
        for (int ks = 0; ks < 4; ++ks) {
            const int cur = ks & 1, nxt = cur ^ 1;
            if (ks < 3) {               // prefetch next k-step's fragments
#pragma unroll
                for (int mt = 0; mt < 4; ++mt)
                    ldsm_x4(afr[nxt][mt][0], afr[nxt][mt][1], afr[nxt][mt][2], afr[nxt][mt][3],
                            sb + aByte[mt] + cAo[ks + 1]);
#pragma unroll
                for (int pp = 0; pp < 2; ++pp)
                    ldsm_x4(bfr[nxt][2 * pp][0], bfr[nxt][2 * pp][1],
                            bfr[nxt][2 * pp + 1][0], bfr[nxt][2 * pp + 1][1],
                            sb + bByte[pp] + cBo[ks + 1]);
            }
#pragma unroll
            for (int mt = 0; mt < 4; ++mt)
#pragma unroll
                for (int nt = 0; nt < 4; ++nt) {
                    asm volatile(
                        "mma.sync.aligned.m16n8k16.row.col.f16.f16.f16.f16 "
                        "{%0,%1}, {%2,%3,%4,%5}, {%6,%7}, {%0,%1};\n"
                        : "+r"(acc[mt][nt][0]), "+r"(acc[mt][nt][1])
                        : "r"(afr[cur][mt][0]), "r"(afr[cur][mt][1]),
                          "r"(afr[cur][mt][2]), "r"(afr[cur][mt][3]),
                          "r"(bfr[cur][nt][0]), "r"(bfr[cur][nt][1]));
                }
        }
    }

    // ---------------- epilogue 1: distances + direct stores ----------------
    float* outB = out + (size_t)b * NPTS * NPTS;
    const uint32_t gi0 = (uint32_t)(ti * 128);
    const uint32_t gj0 = (uint32_t)(tj * 128);

    float dist[4][4][4];
#pragma unroll
    for (int mt = 0; mt < 4; ++mt) {
        const int rl = wm * 64 + mt * 16 + g;
#pragma unroll
        for (int nt = 0; nt < 4; ++nt) {
            const int cl = wn * 32 + nt * 8 + t2;
            const float sb0 = s_sqj[cl],     ib0 = s_invj[cl];
            const float sb1 = s_sqj[cl + 1], ib1 = s_invj[cl + 1];
#pragma unroll
            for (int h = 0; h < 2; ++h) {
                const int rr = rl + h * 8;
                const float sa = s_sqi[rr], ia = s_invi[rr];
                const __half2 hv = *(const __half2*)&acc[mt][nt][h];
                const float2 gf = __half22float2(hv);
                float v0 = hyp_dist(gf.x, sa, sb0, ia, ib0, diagT && (rr == cl));
                float v1 = hyp_dist(gf.y, sa, sb1, ia, ib1, diagT && (rr == cl + 1));
                dist[mt][nt][h * 2 + 0] = v0;
                dist[mt][nt][h * 2 + 1] = v1;
                float2 pk; pk.x = v0; pk.y = v1;
                *(float2*)(outB + ((gi0 + rr) * (uint32_t)NPTS + gj0 + cl)) = pk;
            }
        }
    }

    // ---------------- epilogue 2: mirror via smem staging ------------------
    __syncthreads();                    // gemm smem reads fully done
    for (int jc = 0; jc < 4; ++jc) {    // 4 groups of 32 cols
        if (!diagT && wn == jc) {
#pragma unroll
            for (int mt = 0; mt < 4; ++mt) {
#pragma unroll
                for (int nt = 0; nt < 4; ++nt) {
                    int c = nt * 8 + t2;
                    float* tp = stageT + c * 132;
#pragma unroll
                    for (int h = 0; h < 2; ++h) {
                        int r = wm * 64 + mt * 16 + g + h * 8;
                        tp[r]       = dist[mt][nt][h * 2 + 0];
                        tp[132 + r] = dist[mt][nt][h * 2 + 1];
                    }
                }
            }
        }
        __syncthreads();
        if (!diagT) {
            // 32 rows x 128 floats = 1024 float4, 256 threads x 4
#pragma unroll
            for (int it = 0; it < 4; ++it) {
                int idx = it * 256 + tid;
                int row = idx >> 5;          // 0..31
                int q   = idx & 31;
                float4 v = *(const float4*)&stageT[row * 132 + q * 4];
                uint32_t gj = gj0 + (uint32_t)(jc * 32 + row);
                *(float4*)(outB + (gj * (uint32_t)NPTS + gi0 + (uint32_t)(q * 4))) = v;
            }
        }
        __syncthreads();
    }
}

// -------------------------------------------------------------- launch ----
extern "C" void kernel_launch(void* const* d_in, const int* in_sizes, int n_in,
                              void* d_out, int out_size) {
    const float* emb = (const float*)d_in[0];
    float* out = (float*)d_out;

    prep_kernel<<<BATCH * NPTS, 128>>>(emb);

    cudaFuncSetAttribute(gram_dist_kernel,
                         cudaFuncAttributeMaxDynamicSharedMemorySize, SMEM_DYN);
    dim3 grid(PAIRS, BATCH);
    gram_dist_kernel<<<grid, 256, SMEM_DYN>>>(out);
}